// round 3
// baseline (speedup 1.0000x reference)
#include <cuda_runtime.h>
#include <cuda_bf16.h>
#include <math.h>

#define NN 50000
#define NE 800000
#define HID 128
#define HID2 256
#define STEPS 12
#define DTC 0.5f

// ---------------- scratch (device globals; no allocations allowed) ----------------
__device__ float g_agg[(size_t)NN * HID];     // 25.6 MB
__device__ float g_x1[(size_t)NN * HID2];     // 51.2 MB
__device__ float g_invdeg[NN];
__device__ int   g_degi[NN];
__device__ int   g_rowptr[NN + 1];
__device__ int   g_cursor[NN];
__device__ int   g_srcs[NE];                  // CSR neighbor (src) list grouped by dst

// ---------------- CSR build ----------------
__global__ void k_zero_degi() {
    int i = blockIdx.x * blockDim.x + threadIdx.x;
    if (i < NN) g_degi[i] = 0;
}

// edge_index is int32, layout [2, NE]: row 0 = src, row 1 = dst
__global__ void k_hist(const int* __restrict__ ei) {
    int e = blockIdx.x * blockDim.x + threadIdx.x;
    if (e < NE) atomicAdd(&g_degi[ei[NE + e]], 1);
}

// single-block exclusive scan over 50000 degrees -> rowptr/cursor/invdeg
__global__ void k_scan() {
    __shared__ int part[1024];
    const int C = (NN + 1023) / 1024;  // 49
    int t = threadIdx.x;
    int beg = t * C;
    int end = min(beg + C, NN);
    int s = 0;
    for (int i = beg; i < end; i++) s += g_degi[i];
    part[t] = s;
    __syncthreads();
    // Hillis-Steele inclusive scan over 1024 partials
    for (int off = 1; off < 1024; off <<= 1) {
        int v = (t >= off) ? part[t - off] : 0;
        __syncthreads();
        part[t] += v;
        __syncthreads();
    }
    int run = part[t] - s;  // exclusive prefix for this chunk
    for (int i = beg; i < end; i++) {
        int d = g_degi[i];
        g_rowptr[i] = run;
        g_cursor[i] = run;
        g_invdeg[i] = 1.0f / (float)max(d, 1);
        run += d;
    }
    if (t == 1023) g_rowptr[NN] = NE;
}

__global__ void k_scatter(const int* __restrict__ ei) {
    int e = blockIdx.x * blockDim.x + threadIdx.x;
    if (e < NE) {
        int dst = ei[NE + e];
        int p = atomicAdd(&g_cursor[dst], 1);
        g_srcs[p] = ei[e];
    }
}

// ---------------- aggregation: agg[n] = mean over neighbors of h[src] ----------------
// one warp per node; lane covers 4 of 128 floats (float4)
__global__ void k_aggregate(const float* __restrict__ h) {
    int warp = (blockIdx.x * blockDim.x + threadIdx.x) >> 5;
    int lane = threadIdx.x & 31;
    if (warp >= NN) return;
    int beg = g_rowptr[warp];
    int end = g_rowptr[warp + 1];
    float4 a0 = make_float4(0.f, 0.f, 0.f, 0.f);
    float4 a1 = make_float4(0.f, 0.f, 0.f, 0.f);
    float4 a2 = make_float4(0.f, 0.f, 0.f, 0.f);
    float4 a3 = make_float4(0.f, 0.f, 0.f, 0.f);
    int i = beg;
    for (; i + 3 < end; i += 4) {
        int s0 = g_srcs[i];
        int s1 = g_srcs[i + 1];
        int s2 = g_srcs[i + 2];
        int s3 = g_srcs[i + 3];
        float4 v0 = *(const float4*)&h[(size_t)s0 * HID + lane * 4];
        float4 v1 = *(const float4*)&h[(size_t)s1 * HID + lane * 4];
        float4 v2 = *(const float4*)&h[(size_t)s2 * HID + lane * 4];
        float4 v3 = *(const float4*)&h[(size_t)s3 * HID + lane * 4];
        a0.x += v0.x; a0.y += v0.y; a0.z += v0.z; a0.w += v0.w;
        a1.x += v1.x; a1.y += v1.y; a1.z += v1.z; a1.w += v1.w;
        a2.x += v2.x; a2.y += v2.y; a2.z += v2.z; a2.w += v2.w;
        a3.x += v3.x; a3.y += v3.y; a3.z += v3.z; a3.w += v3.w;
    }
    for (; i < end; i++) {
        int s0 = g_srcs[i];
        float4 v0 = *(const float4*)&h[(size_t)s0 * HID + lane * 4];
        a0.x += v0.x; a0.y += v0.y; a0.z += v0.z; a0.w += v0.w;
    }
    float inv = g_invdeg[warp];
    float4 r;
    r.x = (a0.x + a1.x + a2.x + a3.x) * inv;
    r.y = (a0.y + a1.y + a2.y + a3.y) * inv;
    r.z = (a0.z + a1.z + a2.z + a3.z) * inv;
    r.w = (a0.w + a1.w + a2.w + a3.w) * inv;
    *(float4*)&g_agg[(size_t)warp * HID + lane * 4] = r;
}

// ---------------- fp32 SIMT GEMM with f32x2 packed FMA ----------------
// OUT[r, 0..NOUT) = epi( X[r, 0..K) @ W[K, NOUT] + B )
// EPI 0: tanh          (input transform; OUT = h)
// EPI 1: exact gelu    (OUT = x1)
// EPI 2: Euler update  (d = tanh(.); OUT(=h) = h + (d - decay*h)*dt)
template <int K, int NOUT, int EPI>
__global__ void __launch_bounds__(256, 1) k_gemm(
    const float* __restrict__ X, const float* __restrict__ W,
    const float* __restrict__ B, float* __restrict__ OUT,
    const float* __restrict__ clr, int ntiles)
{
    extern __shared__ float smem[];
    float* Ws = smem;              // K * NOUT
    float* Xs = smem + K * NOUT;   // 64 * K

    const int tid = threadIdx.x;
    const int tx = tid & 31;
    const int ty = tid >> 5;
    constexpr int TJ = NOUT / 64;  // f32x2 pairs per thread (4 or 2)

    // load W once per block (coalesced float4)
    for (int idx = tid * 4; idx < K * NOUT; idx += 256 * 4)
        *(float4*)&Ws[idx] = *(const float4*)&W[idx];

    float decay = 0.f;
    if (EPI == 2) decay = fmaxf(clr[0], 0.f);

    for (int tile = blockIdx.x; tile < ntiles; tile += gridDim.x) {
        const int row0 = tile * 64;
        __syncthreads();  // Xs reuse fence (also fences W load on first iter)
        for (int idx = tid * 4; idx < 64 * K; idx += 256 * 4) {
            int r = idx / K;
            int c = idx - r * K;
            int gr = row0 + r;
            float4 v = make_float4(0.f, 0.f, 0.f, 0.f);
            if (gr < NN) v = *(const float4*)&X[(size_t)gr * K + c];
            *(float4*)&Xs[idx] = v;
        }
        __syncthreads();

        unsigned long long acc[8][TJ];
        #pragma unroll
        for (int i = 0; i < 8; i++)
            #pragma unroll
            for (int j = 0; j < TJ; j++) acc[i][j] = 0ull;

        for (int k = 0; k < K; k += 4) {
            float4 xq[8];
            #pragma unroll
            for (int i = 0; i < 8; i++)
                xq[i] = *(const float4*)&Xs[(ty * 8 + i) * K + k];
            #pragma unroll
            for (int kk = 0; kk < 4; kk++) {
                unsigned long long xd[8];
                #pragma unroll
                for (int i = 0; i < 8; i++) {
                    float xv = (kk == 0) ? xq[i].x : (kk == 1) ? xq[i].y
                             : (kk == 2) ? xq[i].z : xq[i].w;
                    asm("mov.b64 %0, {%1, %1};" : "=l"(xd[i]) : "f"(xv));
                }
                #pragma unroll
                for (int j = 0; j < TJ; j++) {
                    unsigned long long wd =
                        *(const unsigned long long*)&Ws[(k + kk) * NOUT + (tx + j * 32) * 2];
                    #pragma unroll
                    for (int i = 0; i < 8; i++)
                        asm("fma.rn.f32x2 %0, %1, %2, %0;"
                            : "+l"(acc[i][j]) : "l"(xd[i]), "l"(wd));
                }
            }
        }

        #pragma unroll
        for (int i = 0; i < 8; i++) {
            int gr = row0 + ty * 8 + i;
            if (gr < NN) {
                #pragma unroll
                for (int j = 0; j < TJ; j++) {
                    int c = (tx + j * 32) * 2;
                    float lo, hi;
                    asm("mov.b64 {%0, %1}, %2;" : "=f"(lo), "=f"(hi) : "l"(acc[i][j]));
                    float2 b = *(const float2*)&B[c];
                    lo += b.x;
                    hi += b.y;
                    float2 o;
                    if (EPI == 0) {
                        o.x = tanhf(lo);
                        o.y = tanhf(hi);
                    } else if (EPI == 1) {
                        o.x = 0.5f * lo * (1.f + erff(lo * 0.7071067811865475f));
                        o.y = 0.5f * hi * (1.f + erff(hi * 0.7071067811865475f));
                    } else {
                        float2 hv = *(const float2*)&OUT[(size_t)gr * NOUT + c];
                        float dx = tanhf(lo);
                        float dy = tanhf(hi);
                        o.x = hv.x + (dx - decay * hv.x) * DTC;
                        o.y = hv.y + (dy - decay * hv.y) * DTC;
                    }
                    *(float2*)&OUT[(size_t)gr * NOUT + c] = o;
                }
            }
        }
    }
}

// ---------------- launch ----------------
extern "C" void kernel_launch(void* const* d_in, const int* in_sizes, int n_in,
                              void* d_out, int out_size) {
    const float* gat  = (const float*)d_in[0];
    const int*   ei   = (const int*)d_in[1];   // int32 [2, NE]
    const float* W_in = (const float*)d_in[2];
    const float* b_in = (const float*)d_in[3];
    const float* W1   = (const float*)d_in[4];
    const float* b1   = (const float*)d_in[5];
    const float* W2   = (const float*)d_in[6];
    const float* b2   = (const float*)d_in[7];
    const float* clr  = (const float*)d_in[8];
    float* h = (float*)d_out;

    // Resolve device addresses of scratch symbols (host shadow address is
    // NOT valid as a kernel argument).
    float *agg_p = nullptr, *x1_p = nullptr;
    cudaGetSymbolAddress((void**)&agg_p, g_agg);
    cudaGetSymbolAddress((void**)&x1_p, g_x1);

    int sms = 148;
    cudaDeviceGetAttribute(&sms, cudaDevAttrMultiProcessorCount, 0);

    const int SM_IN  = (HID  * HID  + 64 * HID ) * 4;  //  96 KB
    const int SM_G1  = (HID  * HID2 + 64 * HID ) * 4;  // 160 KB
    const int SM_G2  = (HID2 * HID  + 64 * HID2) * 4;  // 192 KB
    cudaFuncSetAttribute(k_gemm<HID,  HID,  0>, cudaFuncAttributeMaxDynamicSharedMemorySize, SM_IN);
    cudaFuncSetAttribute(k_gemm<HID,  HID2, 1>, cudaFuncAttributeMaxDynamicSharedMemorySize, SM_G1);
    cudaFuncSetAttribute(k_gemm<HID2, HID,  2>, cudaFuncAttributeMaxDynamicSharedMemorySize, SM_G2);

    const int ntiles = (NN + 63) / 64;

    // CSR build (once per launch; reused by all 12 steps)
    k_zero_degi<<<(NN + 255) / 256, 256>>>();
    k_hist<<<(NE + 255) / 256, 256>>>(ei);
    k_scan<<<1, 1024>>>();
    k_scatter<<<(NE + 255) / 256, 256>>>(ei);

    // h = tanh(gat_out @ W_in + b_in)
    k_gemm<HID, HID, 0><<<sms, 256, SM_IN>>>(gat, W_in, b_in, h, clr, ntiles);

    const int agg_blocks = (NN * 32 + 255) / 256;
    for (int s = 0; s < STEPS; s++) {
        k_aggregate<<<agg_blocks, 256>>>(h);
        k_gemm<HID, HID2, 1><<<sms, 256, SM_G1>>>(agg_p, W1, b1, x1_p, clr, ntiles);
        k_gemm<HID2, HID, 2><<<sms, 256, SM_G2>>>(x1_p, W2, b2, h, clr, ntiles);
    }
}

// round 5
// speedup vs baseline: 1.4827x; 1.4827x over previous
#include <cuda_runtime.h>
#include <cuda_bf16.h>
#include <math.h>
#include <stdint.h>

#define NN 50000
#define NE 800000
#define HID 128
#define HID2 256
#define STEPS 12
#define DTC 0.5f

// ================= scratch =================
__device__ float   g_agg[(size_t)NN * HID];
__device__ float   g_x1[(size_t)NN * HID2];
__device__ float   g_invdeg[NN];
__device__ int     g_degi[NN];
__device__ int     g_rowptr[NN + 1];
__device__ int     g_cursor[NN];
__device__ int     g_srcs[NE];
// pre-swizzled bf16 hi/lo weight images ([N][K] layout, 16B-unit XOR swizzle)
__device__ uint8_t g_Wimg_in[2 * 128 * 128 * 2];   //  64 KB
__device__ uint8_t g_Wimg1[2 * 256 * 128 * 2];     // 128 KB
__device__ uint8_t g_Wimg2[2 * 128 * 256 * 2];     // 128 KB

// ================= CSR build =================
__global__ void k_zero_degi() {
    int i = blockIdx.x * blockDim.x + threadIdx.x;
    if (i < NN) g_degi[i] = 0;
}
__global__ void k_hist(const int* __restrict__ ei) {
    int e = blockIdx.x * blockDim.x + threadIdx.x;
    if (e < NE) atomicAdd(&g_degi[ei[NE + e]], 1);
}
__global__ void k_scan() {
    __shared__ int part[1024];
    const int C = (NN + 1023) / 1024;
    int t = threadIdx.x;
    int beg = t * C, end = min(beg + C, NN);
    int s = 0;
    for (int i = beg; i < end; i++) s += g_degi[i];
    part[t] = s;
    __syncthreads();
    for (int off = 1; off < 1024; off <<= 1) {
        int v = (t >= off) ? part[t - off] : 0;
        __syncthreads();
        part[t] += v;
        __syncthreads();
    }
    int run = part[t] - s;
    for (int i = beg; i < end; i++) {
        int d = g_degi[i];
        g_rowptr[i] = run;
        g_cursor[i] = run;
        g_invdeg[i] = 1.0f / (float)max(d, 1);
        run += d;
    }
    if (t == 1023) g_rowptr[NN] = NE;
}
__global__ void k_scatter(const int* __restrict__ ei) {
    int e = blockIdx.x * blockDim.x + threadIdx.x;
    if (e < NE) {
        int dst = ei[NE + e];
        int p = atomicAdd(&g_cursor[dst], 1);
        g_srcs[p] = ei[e];
    }
}

// ================= aggregation =================
__global__ void k_aggregate(const float* __restrict__ h) {
    int warp = (blockIdx.x * blockDim.x + threadIdx.x) >> 5;
    int lane = threadIdx.x & 31;
    if (warp >= NN) return;
    int beg = g_rowptr[warp], end = g_rowptr[warp + 1];
    float4 a0 = make_float4(0.f, 0.f, 0.f, 0.f);
    float4 a1 = a0, a2 = a0, a3 = a0;
    int i = beg;
    for (; i + 3 < end; i += 4) {
        int s0 = g_srcs[i], s1 = g_srcs[i + 1], s2 = g_srcs[i + 2], s3 = g_srcs[i + 3];
        float4 v0 = *(const float4*)&h[(size_t)s0 * HID + lane * 4];
        float4 v1 = *(const float4*)&h[(size_t)s1 * HID + lane * 4];
        float4 v2 = *(const float4*)&h[(size_t)s2 * HID + lane * 4];
        float4 v3 = *(const float4*)&h[(size_t)s3 * HID + lane * 4];
        a0.x += v0.x; a0.y += v0.y; a0.z += v0.z; a0.w += v0.w;
        a1.x += v1.x; a1.y += v1.y; a1.z += v1.z; a1.w += v1.w;
        a2.x += v2.x; a2.y += v2.y; a2.z += v2.z; a2.w += v2.w;
        a3.x += v3.x; a3.y += v3.y; a3.z += v3.z; a3.w += v3.w;
    }
    for (; i < end; i++) {
        float4 v0 = *(const float4*)&h[(size_t)g_srcs[i] * HID + lane * 4];
        a0.x += v0.x; a0.y += v0.y; a0.z += v0.z; a0.w += v0.w;
    }
    float inv = g_invdeg[warp];
    float4 r;
    r.x = (a0.x + a1.x + a2.x + a3.x) * inv;
    r.y = (a0.y + a1.y + a2.y + a3.y) * inv;
    r.z = (a0.z + a1.z + a2.z + a3.z) * inv;
    r.w = (a0.w + a1.w + a2.w + a3.w) * inv;
    *(float4*)&g_agg[(size_t)warp * HID + lane * 4] = r;
}

// ================= weight image prep =================
// W [K, NOUT] row-major -> Wt [NOUT][K] bf16 hi block then lo block.
// 16-byte units (8 bf16); per-row swizzle: phys_unit = ku ^ (n & 7).
__global__ void k_prepw(const float* __restrict__ W, uint8_t* __restrict__ img,
                        int K, int NOUT) {
    int idx = blockIdx.x * blockDim.x + threadIdx.x;
    if (idx >= K * NOUT) return;
    int k = idx / NOUT, n = idx % NOUT;
    float v = W[idx];
    __nv_bfloat16 hi = __float2bfloat16(v);
    __nv_bfloat16 lo = __float2bfloat16(v - __bfloat162float(hi));
    int SUW = K >> 3;
    size_t unit = (size_t)n * SUW + ((k >> 3) ^ (n & 7));
    size_t byteo = unit * 16 + (size_t)(k & 7) * 2;
    *(__nv_bfloat16*)(img + byteo) = hi;
    *(__nv_bfloat16*)(img + (size_t)NOUT * K * 2 + byteo) = lo;
}

// ================= mma.sync helpers =================
__device__ __forceinline__ uint32_t smem_u32(const void* p) {
    uint32_t a;
    asm("{ .reg .u64 t; cvta.to.shared.u64 t, %1; cvt.u32.u64 %0, t; }" : "=r"(a) : "l"(p));
    return a;
}
__device__ __forceinline__ void ldmx4(uint32_t* r, uint32_t addr) {
    asm volatile("ldmatrix.sync.aligned.m8n8.x4.shared.b16 {%0,%1,%2,%3}, [%4];"
                 : "=r"(r[0]), "=r"(r[1]), "=r"(r[2]), "=r"(r[3]) : "r"(addr));
}
__device__ __forceinline__ void mma16816(float* c, const uint32_t* a, uint32_t b0, uint32_t b1) {
    asm volatile(
        "mma.sync.aligned.m16n8k16.row.col.f32.bf16.bf16.f32 "
        "{%0,%1,%2,%3}, {%4,%5,%6,%7}, {%8,%9}, {%0,%1,%2,%3};"
        : "+f"(c[0]), "+f"(c[1]), "+f"(c[2]), "+f"(c[3])
        : "r"(a[0]), "r"(a[1]), "r"(a[2]), "r"(a[3]), "r"(b0), "r"(b1));
}

// ================= HMMA GEMM with fused epilogue =================
// OUT[r,:] = epi( X[r,:K] @ W[K,NOUT] + B ), hi/lo bf16 split (3 MMA terms)
// EPI 0: tanh -> h ; EPI 1: exact gelu -> x1 ; EPI 2: Euler update on h
template <int K, int NB, int EPI>
__global__ void __launch_bounds__(256, 1) k_mgemm(
    const float* __restrict__ X, const uint8_t* __restrict__ Wimg,
    const float* __restrict__ Bb, float* __restrict__ OUT,
    const float* __restrict__ clr, int ntiles)
{
    constexpr int NOUT = NB * 128;
    constexpr int NCHUNK = K / 128;     // A processed in 128-wide K chunks
    constexpr int SUW = K / 8;          // 16B units per W row
    constexpr int AUNITS = 128 * 16;    // A chunk: 128 rows x 16 units (hi or lo)
    extern __shared__ char smem[];
    uint4* Ah = (uint4*)smem;                 // AUNITS
    uint4* Al = Ah + AUNITS;                  // AUNITS
    uint4* Wh = Al + AUNITS;                  // NOUT*SUW units (hi), then lo
    const uint32_t ah_b = smem_u32(Ah);
    const uint32_t al_b = smem_u32(Al);
    const uint32_t wh_b = smem_u32(Wh);
    const uint32_t wl_b = wh_b + NOUT * SUW * 16;

    const int tid = threadIdx.x;
    const int lane = tid & 31;
    const int wid = tid >> 5;
    const int wm = wid & 3;             // 4 warps over M (32 rows each)
    const int wn = wid >> 2;            // 2 warps over N (64 cols each)
    const int r8 = lane & 7;
    const int quad = lane >> 3;
    const int g = lane >> 2;
    const int tq = lane & 3;

    // copy pre-swizzled W (hi+lo) into smem
    for (int i = tid; i < 2 * NOUT * SUW; i += 256)
        Wh[i] = ((const uint4*)Wimg)[i];

    float decay = 0.f;
    if (EPI == 2) decay = fmaxf(clr[0], 0.f);

    for (int tile = blockIdx.x; tile < ntiles; tile += gridDim.x) {
        const int row0 = tile * 128;
        #pragma unroll 1
        for (int nb = 0; nb < NB; nb++) {
            float acc[2][8][4];
            #pragma unroll
            for (int a = 0; a < 2; a++)
                #pragma unroll
                for (int b = 0; b < 8; b++)
                    #pragma unroll
                    for (int c = 0; c < 4; c++) acc[a][b][c] = 0.f;

            #pragma unroll 1
            for (int chunk = 0; chunk < NCHUNK; chunk++) {
                if (nb == 0) {
                    // load & split A chunk [128 x 128] fp32 -> bf16 hi/lo
                    __syncthreads();
                    #pragma unroll 1
                    for (int u = tid; u < AUNITS; u += 256) {
                        int r = u >> 4, ku = u & 15;
                        int gr = row0 + r;
                        float4 v0 = make_float4(0.f, 0.f, 0.f, 0.f), v1 = v0;
                        if (gr < NN) {
                            const float* xp = &X[(size_t)gr * K + chunk * 128 + ku * 8];
                            v0 = *(const float4*)xp;
                            v1 = *(const float4*)(xp + 4);
                        }
                        __nv_bfloat16 h0 = __float2bfloat16(v0.x), h1 = __float2bfloat16(v0.y);
                        __nv_bfloat16 h2 = __float2bfloat16(v0.z), h3 = __float2bfloat16(v0.w);
                        __nv_bfloat16 h4 = __float2bfloat16(v1.x), h5 = __float2bfloat16(v1.y);
                        __nv_bfloat16 h6 = __float2bfloat16(v1.z), h7 = __float2bfloat16(v1.w);
                        ushort4 H0, H1, L0, L1;
                        H0.x = __bfloat16_as_ushort(h0); H0.y = __bfloat16_as_ushort(h1);
                        H0.z = __bfloat16_as_ushort(h2); H0.w = __bfloat16_as_ushort(h3);
                        H1.x = __bfloat16_as_ushort(h4); H1.y = __bfloat16_as_ushort(h5);
                        H1.z = __bfloat16_as_ushort(h6); H1.w = __bfloat16_as_ushort(h7);
                        L0.x = __bfloat16_as_ushort(__float2bfloat16(v0.x - __bfloat162float(h0)));
                        L0.y = __bfloat16_as_ushort(__float2bfloat16(v0.y - __bfloat162float(h1)));
                        L0.z = __bfloat16_as_ushort(__float2bfloat16(v0.z - __bfloat162float(h2)));
                        L0.w = __bfloat16_as_ushort(__float2bfloat16(v0.w - __bfloat162float(h3)));
                        L1.x = __bfloat16_as_ushort(__float2bfloat16(v1.x - __bfloat162float(h4)));
                        L1.y = __bfloat16_as_ushort(__float2bfloat16(v1.y - __bfloat162float(h5)));
                        L1.z = __bfloat16_as_ushort(__float2bfloat16(v1.z - __bfloat162float(h6)));
                        L1.w = __bfloat16_as_ushort(__float2bfloat16(v1.w - __bfloat162float(h7)));
                        int phys = (r << 4) + (ku ^ (r & 7));
                        ((ushort4*)Ah)[phys * 2 + 0] = H0;
                        ((ushort4*)Ah)[phys * 2 + 1] = H1;
                        ((ushort4*)Al)[phys * 2 + 0] = L0;
                        ((ushort4*)Al)[phys * 2 + 1] = L1;
                    }
                    __syncthreads();
                }

                #pragma unroll
                for (int ks = 0; ks < 8; ks++) {
                    // A fragments (hi & lo) for 2 m-tiles
                    uint32_t a_hi[2][4], a_lo[2][4];
                    #pragma unroll
                    for (int mt = 0; mt < 2; mt++) {
                        int row = wm * 32 + mt * 16 + r8 + (quad & 1) * 8;
                        int ku = 2 * ks + (quad >> 1);
                        uint32_t off = ((row << 4) + (ku ^ (row & 7))) * 16;
                        ldmx4(a_hi[mt], ah_b + off);
                        ldmx4(a_lo[mt], al_b + off);
                    }
                    // B fragments: 4 groups of 2 n-tiles
                    #pragma unroll
                    for (int nt2 = 0; nt2 < 4; nt2++) {
                        int nrow = nb * 128 + wn * 64 + nt2 * 16 + r8 + (quad >> 1) * 8;
                        int ku = chunk * 16 + 2 * ks + (quad & 1);
                        uint32_t off = ((uint32_t)nrow * SUW + (ku ^ (nrow & 7))) * 16;
                        uint32_t bh[4], bl[4];
                        ldmx4(bh, wh_b + off);
                        ldmx4(bl, wl_b + off);
                        #pragma unroll
                        for (int mt = 0; mt < 2; mt++) {
                            mma16816(acc[mt][2 * nt2 + 0], a_hi[mt], bh[0], bh[1]);
                            mma16816(acc[mt][2 * nt2 + 0], a_lo[mt], bh[0], bh[1]);
                            mma16816(acc[mt][2 * nt2 + 0], a_hi[mt], bl[0], bl[1]);
                            mma16816(acc[mt][2 * nt2 + 1], a_hi[mt], bh[2], bh[3]);
                            mma16816(acc[mt][2 * nt2 + 1], a_lo[mt], bh[2], bh[3]);
                            mma16816(acc[mt][2 * nt2 + 1], a_hi[mt], bl[2], bl[3]);
                        }
                    }
                }
            }

            // ---- epilogue ----
            #pragma unroll
            for (int mt = 0; mt < 2; mt++) {
                int rbase = row0 + wm * 32 + mt * 16 + g;
                #pragma unroll
                for (int nt = 0; nt < 8; nt++) {
                    int col = nb * 128 + wn * 64 + nt * 8 + 2 * tq;
                    float2 bb = *(const float2*)&Bb[col];
                    #pragma unroll
                    for (int half = 0; half < 2; half++) {
                        int row = rbase + half * 8;
                        if (row >= NN) continue;
                        float x0 = acc[mt][nt][2 * half + 0] + bb.x;
                        float x1 = acc[mt][nt][2 * half + 1] + bb.y;
                        float2 o;
                        if (EPI == 0) {
                            o.x = tanhf(x0);
                            o.y = tanhf(x1);
                        } else if (EPI == 1) {
                            const float c = 0.7071067811865475f;
                            o.x = 0.5f * x0 * (1.f + erff(x0 * c));
                            o.y = 0.5f * x1 * (1.f + erff(x1 * c));
                        } else {
                            float2 hv = *(const float2*)&OUT[(size_t)row * NOUT + col];
                            o.x = hv.x + (tanhf(x0) - decay * hv.x) * DTC;
                            o.y = hv.y + (tanhf(x1) - decay * hv.y) * DTC;
                        }
                        *(float2*)&OUT[(size_t)row * NOUT + col] = o;
                    }
                }
            }
        }
    }
}

// ================= launch =================
extern "C" void kernel_launch(void* const* d_in, const int* in_sizes, int n_in,
                              void* d_out, int out_size) {
    const float* gat  = (const float*)d_in[0];
    const int*   ei   = (const int*)d_in[1];
    const float* W_in = (const float*)d_in[2];
    const float* b_in = (const float*)d_in[3];
    const float* W1   = (const float*)d_in[4];
    const float* b1   = (const float*)d_in[5];
    const float* W2   = (const float*)d_in[6];
    const float* b2   = (const float*)d_in[7];
    const float* clr  = (const float*)d_in[8];
    float* h = (float*)d_out;

    float *agg_p = nullptr, *x1_p = nullptr;
    uint8_t *wi_in = nullptr, *wi_1 = nullptr, *wi_2 = nullptr;
    cudaGetSymbolAddress((void**)&agg_p, g_agg);
    cudaGetSymbolAddress((void**)&x1_p, g_x1);
    cudaGetSymbolAddress((void**)&wi_in, g_Wimg_in);
    cudaGetSymbolAddress((void**)&wi_1, g_Wimg1);
    cudaGetSymbolAddress((void**)&wi_2, g_Wimg2);

    int sms = 148;
    cudaDeviceGetAttribute(&sms, cudaDevAttrMultiProcessorCount, 0);

    // smem: A hi/lo (64KB) + W hi/lo
    const int SM_IN = 65536 + 65536;    // 128 KB
    const int SM_G1 = 65536 + 131072;   // 192 KB
    const int SM_G2 = 65536 + 131072;   // 192 KB
    cudaFuncSetAttribute(k_mgemm<128, 1, 0>, cudaFuncAttributeMaxDynamicSharedMemorySize, SM_IN);
    cudaFuncSetAttribute(k_mgemm<128, 2, 1>, cudaFuncAttributeMaxDynamicSharedMemorySize, SM_G1);
    cudaFuncSetAttribute(k_mgemm<256, 1, 2>, cudaFuncAttributeMaxDynamicSharedMemorySize, SM_G2);

    const int ntiles = (NN + 127) / 128;   // 391
    const int grid = (ntiles < sms) ? ntiles : sms;

    // CSR build + weight image prep (once per launch)
    k_zero_degi<<<(NN + 255) / 256, 256>>>();
    k_hist<<<(NE + 255) / 256, 256>>>(ei);
    k_scan<<<1, 1024>>>();
    k_scatter<<<(NE + 255) / 256, 256>>>(ei);
    k_prepw<<<(128 * 128 + 255) / 256, 256>>>(W_in, wi_in, 128, 128);
    k_prepw<<<(128 * 256 + 255) / 256, 256>>>(W1, wi_1, 128, 256);
    k_prepw<<<(256 * 128 + 255) / 256, 256>>>(W2, wi_2, 256, 128);

    // h = tanh(gat @ W_in + b_in)
    k_mgemm<128, 1, 0><<<grid, 256, SM_IN>>>(gat, wi_in, b_in, h, clr, ntiles);

    const int agg_blocks = (NN * 32 + 255) / 256;
    for (int s = 0; s < STEPS; s++) {
        k_aggregate<<<agg_blocks, 256>>>(h);
        k_mgemm<128, 2, 1><<<grid, 256, SM_G1>>>(agg_p, wi_1, b1, x1_p, clr, ntiles);
        k_mgemm<256, 1, 2><<<grid, 256, SM_G2>>>(x1_p, wi_2, b2, h, clr, ntiles);
    }
}